// round 2
// baseline (speedup 1.0000x reference)
#include <cuda_runtime.h>

#define N_NODES 100000
#define N_EDGES 300000
#define IN_CH   256
#define HID     256
#define NCOLS   512   // [a | b] per node

// Scratch (allocation-free rule: __device__ globals)
__device__ float g_C[(size_t)N_NODES * NCOLS];   // 204.8 MB
__device__ float g_Wt[IN_CH * NCOLS];            // rearranged W1, K-major

// ---------------------------------------------------------------------------
// Rearrange W1 [HID, 2*IN_CH] row-major into Wt[d][j]:
//   j <  256: Wt[d][j] = W1[j][d]         (W1s, for a = z @ W1s^T)
//   j >= 256: Wt[d][j] = W1[j-256][256+d] (W1d, for b = z @ W1d^T)
// ---------------------------------------------------------------------------
__global__ void prep_w_kernel(const float* __restrict__ W1) {
    int idx = blockIdx.x * blockDim.x + threadIdx.x;
    if (idx >= IN_CH * NCOLS) return;
    int d = idx / NCOLS;
    int j = idx % NCOLS;
    int h   = j & 255;
    int off = (j >> 8) << 8;   // 0 or 256
    g_Wt[idx] = W1[h * 512 + off + d];
}

// ---------------------------------------------------------------------------
// GEMM: g_C[M, 512] = z[M, 256] @ Wt[256, 512]
// Block tile 128x128, BK=16, 256 threads, 8x8 per thread.
// ---------------------------------------------------------------------------
#define BM 128
#define BN 128
#define BK 16
#define TM 8
#define TN 8

__global__ __launch_bounds__(256) void gemm_kernel(const float* __restrict__ A) {
    __shared__ float As[BK][BM];
    __shared__ float Bs[BK][BN];

    const int bx = blockIdx.x;           // N tile (0..3)
    const int by = blockIdx.y;           // M tile
    const int tid = threadIdx.x;
    const int tx = tid & 15;             // 0..15 -> N micro
    const int ty = tid >> 4;             // 0..15 -> M micro
    const int rowBase = by * BM;

    float acc[TM][TN];
    #pragma unroll
    for (int i = 0; i < TM; i++)
        #pragma unroll
        for (int j = 0; j < TN; j++)
            acc[i][j] = 0.f;

    for (int k0 = 0; k0 < IN_CH; k0 += BK) {
        // Load A tile (128 rows x 16 k), transpose into As[k][m]
        #pragma unroll
        for (int i = 0; i < 2; i++) {
            int lin = tid + i * 256;         // 0..511 float4 slots
            int ar  = lin >> 2;              // 0..127
            int ac  = (lin & 3) << 2;        // 0,4,8,12
            int grow = rowBase + ar;
            float4 v = make_float4(0.f, 0.f, 0.f, 0.f);
            if (grow < N_NODES)
                v = *(const float4*)&A[(size_t)grow * IN_CH + k0 + ac];
            As[ac + 0][ar] = v.x;
            As[ac + 1][ar] = v.y;
            As[ac + 2][ar] = v.z;
            As[ac + 3][ar] = v.w;
        }
        // Load B tile (16 k x 128 n), row-major
        #pragma unroll
        for (int i = 0; i < 2; i++) {
            int lin = tid + i * 256;
            int br  = lin >> 5;              // 0..15
            int bc  = (lin & 31) << 2;       // 0..124
            *(float4*)&Bs[br][bc] =
                *(const float4*)&g_Wt[(k0 + br) * NCOLS + bx * BN + bc];
        }
        __syncthreads();

        #pragma unroll
        for (int k = 0; k < BK; k++) {
            float a[TM], b[TN];
            #pragma unroll
            for (int i = 0; i < TM; i += 4)
                *(float4*)&a[i] = *(const float4*)&As[k][ty * TM + i];
            #pragma unroll
            for (int j = 0; j < TN; j += 4)
                *(float4*)&b[j] = *(const float4*)&Bs[k][tx * TN + j];
            #pragma unroll
            for (int i = 0; i < TM; i++)
                #pragma unroll
                for (int j = 0; j < TN; j++)
                    acc[i][j] = fmaf(a[i], b[j], acc[i][j]);
        }
        __syncthreads();
    }

    // Store
    #pragma unroll
    for (int i = 0; i < TM; i++) {
        int grow = rowBase + ty * TM + i;
        if (grow < N_NODES) {
            size_t base = (size_t)grow * NCOLS + bx * BN + tx * TN;
            #pragma unroll
            for (int j = 0; j < TN; j += 4)
                *(float4*)&g_C[base + j] = *(float4*)&acc[i][j];
        }
    }
}

// ---------------------------------------------------------------------------
// Edge kernel: one warp per edge.
// out[e] = b2 + sum_h W2[h] * relu(C[src][h] + C[dst][256+h] + b1[h])
// edge_index arrives as int32 (harness downcasts the reference's int64).
// ---------------------------------------------------------------------------
__global__ __launch_bounds__(256) void edge_kernel(
    const int* __restrict__ ei,
    const float* __restrict__ b1,
    const float* __restrict__ W2,
    const float* __restrict__ b2,
    float* __restrict__ out)
{
    int gwarp = (blockIdx.x * blockDim.x + threadIdx.x) >> 5;
    int lane  = threadIdx.x & 31;
    if (gwarp >= N_EDGES) return;

    int s = ei[gwarp];             // edge_index[0][e]
    int d = ei[N_EDGES + gwarp];   // edge_index[1][e]

    const float* arow = &g_C[(size_t)s * NCOLS];
    const float* brow = &g_C[(size_t)d * NCOLS + HID];

    float sum = 0.f;
    #pragma unroll
    for (int i = 0; i < 2; i++) {
        int h = (lane + i * 32) << 2;    // 0..252, step 4
        float4 av  = *(const float4*)&arow[h];
        float4 bv  = *(const float4*)&brow[h];
        float4 b1v = *(const float4*)&b1[h];
        float4 w2v = *(const float4*)&W2[h];
        sum = fmaf(w2v.x, fmaxf(av.x + bv.x + b1v.x, 0.f), sum);
        sum = fmaf(w2v.y, fmaxf(av.y + bv.y + b1v.y, 0.f), sum);
        sum = fmaf(w2v.z, fmaxf(av.z + bv.z + b1v.z, 0.f), sum);
        sum = fmaf(w2v.w, fmaxf(av.w + bv.w + b1v.w, 0.f), sum);
    }
    #pragma unroll
    for (int o = 16; o; o >>= 1)
        sum += __shfl_xor_sync(0xFFFFFFFFu, sum, o);

    if (lane == 0)
        out[gwarp] = sum + b2[0];
}

// ---------------------------------------------------------------------------
extern "C" void kernel_launch(void* const* d_in, const int* in_sizes, int n_in,
                              void* d_out, int out_size)
{
    const float* z   = (const float*)d_in[0];      // [100000, 256]
    const float* W1  = (const float*)d_in[1];      // [256, 512]
    const float* b1  = (const float*)d_in[2];      // [256]
    const float* W2  = (const float*)d_in[3];      // [256]
    const float* b2  = (const float*)d_in[4];      // [1]
    const int*   ei  = (const int*)d_in[5];        // [2, 300000] int32
    float*       out = (float*)d_out;              // [300000]

    prep_w_kernel<<<(IN_CH * NCOLS + 255) / 256, 256>>>(W1);

    dim3 grid(NCOLS / BN, (N_NODES + BM - 1) / BM);
    gemm_kernel<<<grid, 256>>>(z);

    int edge_blocks = (N_EDGES * 32 + 255) / 256;
    edge_kernel<<<edge_blocks, 256>>>(ei, b1, W2, b2, out);
}

// round 4
// speedup vs baseline: 1.7682x; 1.7682x over previous
#include <cuda_runtime.h>
#include <cstdint>

#define N_NODES 100000
#define N_EDGES 300000
#define IN_CH   256
#define NCOLS   512

// Scratch (__device__ globals; no allocs allowed)
__device__ float g_C[(size_t)N_NODES * NCOLS];   // layer-1 pre-activation per node
__device__ float g_Bt[NCOLS * IN_CH];            // B[n][k] tf32-rounded:
                                                 //   n<256: W1[n][k]; n>=256: W1[n-256][256+k]

__device__ __forceinline__ float tf32r(float x) {
    uint32_t t;
    asm("cvt.rna.tf32.f32 %0, %1;" : "=r"(t) : "f"(x));
    return __uint_as_float(t);
}

// ---------------------------------------------------------------------------
// Prep: B[n][k] = tf32_rna( n<256 ? W1[n][k] : W1[n-256][256+k] )
// ---------------------------------------------------------------------------
__global__ void prep_b_kernel(const float* __restrict__ W1) {
    int idx = blockIdx.x * blockDim.x + threadIdx.x;
    if (idx >= NCOLS * IN_CH) return;
    int n = idx >> 8;
    int k = idx & 255;
    int h    = n & 255;
    int half = n >> 8;
    g_Bt[idx] = tf32r(W1[h * 512 + half * 256 + k]);
}

// ---------------------------------------------------------------------------
// tf32 mma.sync GEMM: g_C[M,512] = tf32(z[M,256]) @ g_Bt[512,256]^T
// CTA tile 128x128, BK=16, 256 threads (8 warps 2x4), warp tile 64x32.
// mma.sync.aligned.m16n8k8.row.col.f32.tf32.tf32.f32
// ---------------------------------------------------------------------------
#define BM 128
#define BN 128
#define BK 16
#define LDK 20              // padded K stride (floats) -> conflict-free frag reads
#define KTILES (IN_CH / BK) // 16

__global__ __launch_bounds__(256, 1) void gemm_mma_kernel(const float* __restrict__ z) {
    __shared__ float As[2][BM][LDK];
    __shared__ float Bs[2][BN][LDK];

    const int tid = threadIdx.x;
    const int wid = tid >> 5;
    const int lane = tid & 31;
    const int g = lane >> 2;        // group 0..7
    const int t = lane & 3;         // thread-in-group 0..3
    const int wm = (wid >> 2) * 64; // warp M offset in tile (0,64)
    const int wn = (wid & 3) * 32;  // warp N offset in tile (0..96)

    const int m0 = blockIdx.y * BM;
    const int n0 = blockIdx.x * BN;

    // Global load indices (2 float4 per thread per tile, per matrix)
    const int r0 = tid >> 2;              // 0..63
    const int r1 = r0 + 64;               // 64..127
    const int kq = (tid & 3) << 2;        // 0,4,8,12

    float c[4][4][4];
    #pragma unroll
    for (int i = 0; i < 4; i++)
        #pragma unroll
        for (int j = 0; j < 4; j++)
            #pragma unroll
            for (int r = 0; r < 4; r++)
                c[i][j][r] = 0.f;

    const bool okA0 = (m0 + r0) < N_NODES;
    const bool okA1 = (m0 + r1) < N_NODES;
    const float* aptr0 = z + (size_t)(m0 + r0) * IN_CH + kq;
    const float* aptr1 = z + (size_t)(m0 + r1) * IN_CH + kq;
    const float* bptr0 = g_Bt + (size_t)(n0 + r0) * IN_CH + kq;
    const float* bptr1 = g_Bt + (size_t)(n0 + r1) * IN_CH + kq;

    float4 av0, av1, bv0, bv1;
    const float4 zero4 = make_float4(0.f, 0.f, 0.f, 0.f);

    // Prologue: tile 0
    av0 = okA0 ? *(const float4*)(aptr0) : zero4;
    av1 = okA1 ? *(const float4*)(aptr1) : zero4;
    bv0 = *(const float4*)(bptr0);
    bv1 = *(const float4*)(bptr1);
    av0.x = tf32r(av0.x); av0.y = tf32r(av0.y); av0.z = tf32r(av0.z); av0.w = tf32r(av0.w);
    av1.x = tf32r(av1.x); av1.y = tf32r(av1.y); av1.z = tf32r(av1.z); av1.w = tf32r(av1.w);
    *(float4*)&As[0][r0][kq] = av0;
    *(float4*)&As[0][r1][kq] = av1;
    *(float4*)&Bs[0][r0][kq] = bv0;
    *(float4*)&Bs[0][r1][kq] = bv1;
    __syncthreads();

    for (int kt = 0; kt < KTILES; kt++) {
        const int buf = kt & 1;

        if (kt + 1 < KTILES) {
            const int koff = (kt + 1) * BK;
            av0 = okA0 ? *(const float4*)(aptr0 + koff) : zero4;
            av1 = okA1 ? *(const float4*)(aptr1 + koff) : zero4;
            bv0 = *(const float4*)(bptr0 + koff);
            bv1 = *(const float4*)(bptr1 + koff);
        }

        // Compute on smem[buf]: 2 k-steps of 8
        #pragma unroll
        for (int kk = 0; kk < 2; kk++) {
            const int kb = kk * 8;
            uint32_t bf[4][2];
            #pragma unroll
            for (int nf = 0; nf < 4; nf++) {
                bf[nf][0] = __float_as_uint(Bs[buf][wn + nf * 8 + g][kb + t]);
                bf[nf][1] = __float_as_uint(Bs[buf][wn + nf * 8 + g][kb + t + 4]);
            }
            #pragma unroll
            for (int mf = 0; mf < 4; mf++) {
                const int ar = wm + mf * 16 + g;
                uint32_t a0 = __float_as_uint(As[buf][ar][kb + t]);
                uint32_t a1 = __float_as_uint(As[buf][ar + 8][kb + t]);
                uint32_t a2 = __float_as_uint(As[buf][ar][kb + t + 4]);
                uint32_t a3 = __float_as_uint(As[buf][ar + 8][kb + t + 4]);
                #pragma unroll
                for (int nf = 0; nf < 4; nf++) {
                    asm volatile(
                        "mma.sync.aligned.m16n8k8.row.col.f32.tf32.tf32.f32 "
                        "{%0,%1,%2,%3}, {%4,%5,%6,%7}, {%8,%9}, {%0,%1,%2,%3};"
                        : "+f"(c[mf][nf][0]), "+f"(c[mf][nf][1]),
                          "+f"(c[mf][nf][2]), "+f"(c[mf][nf][3])
                        : "r"(a0), "r"(a1), "r"(a2), "r"(a3),
                          "r"(bf[nf][0]), "r"(bf[nf][1]));
                }
            }
        }

        if (kt + 1 < KTILES) {
            av0.x = tf32r(av0.x); av0.y = tf32r(av0.y); av0.z = tf32r(av0.z); av0.w = tf32r(av0.w);
            av1.x = tf32r(av1.x); av1.y = tf32r(av1.y); av1.z = tf32r(av1.z); av1.w = tf32r(av1.w);
            const int nb = buf ^ 1;
            *(float4*)&As[nb][r0][kq] = av0;
            *(float4*)&As[nb][r1][kq] = av1;
            *(float4*)&Bs[nb][r0][kq] = bv0;
            *(float4*)&Bs[nb][r1][kq] = bv1;
        }
        __syncthreads();
    }

    // Epilogue: c[mf][nf][r] -> g_C
    #pragma unroll
    for (int mf = 0; mf < 4; mf++) {
        const int row_a = m0 + wm + mf * 16 + g;
        const int row_b = row_a + 8;
        #pragma unroll
        for (int nf = 0; nf < 4; nf++) {
            const int col = n0 + wn + nf * 8 + t * 2;
            if (row_a < N_NODES)
                *(float2*)&g_C[(size_t)row_a * NCOLS + col] =
                    make_float2(c[mf][nf][0], c[mf][nf][1]);
            if (row_b < N_NODES)
                *(float2*)&g_C[(size_t)row_b * NCOLS + col] =
                    make_float2(c[mf][nf][2], c[mf][nf][3]);
        }
    }
}

// ---------------------------------------------------------------------------
// Edge kernel: one warp per edge.
// out[e] = b2 + sum_h W2[h] * relu(C[src][h] + C[dst][256+h] + b1[h])
// ---------------------------------------------------------------------------
__global__ __launch_bounds__(256) void edge_kernel(
    const int* __restrict__ ei,
    const float* __restrict__ b1,
    const float* __restrict__ W2,
    const float* __restrict__ b2,
    float* __restrict__ out)
{
    int gwarp = (blockIdx.x * blockDim.x + threadIdx.x) >> 5;
    int lane  = threadIdx.x & 31;
    if (gwarp >= N_EDGES) return;

    int s = ei[gwarp];
    int d = ei[N_EDGES + gwarp];

    const float* arow = &g_C[(size_t)s * NCOLS];
    const float* brow = &g_C[(size_t)d * NCOLS + IN_CH];

    float sum = 0.f;
    #pragma unroll
    for (int i = 0; i < 2; i++) {
        int h = (lane + i * 32) << 2;
        float4 av  = *(const float4*)&arow[h];
        float4 bv  = *(const float4*)&brow[h];
        float4 b1v = *(const float4*)&b1[h];
        float4 w2v = *(const float4*)&W2[h];
        sum = fmaf(w2v.x, fmaxf(av.x + bv.x + b1v.x, 0.f), sum);
        sum = fmaf(w2v.y, fmaxf(av.y + bv.y + b1v.y, 0.f), sum);
        sum = fmaf(w2v.z, fmaxf(av.z + bv.z + b1v.z, 0.f), sum);
        sum = fmaf(w2v.w, fmaxf(av.w + bv.w + b1v.w, 0.f), sum);
    }
    #pragma unroll
    for (int o = 16; o; o >>= 1)
        sum += __shfl_xor_sync(0xFFFFFFFFu, sum, o);

    if (lane == 0)
        out[gwarp] = sum + b2[0];
}

// ---------------------------------------------------------------------------
extern "C" void kernel_launch(void* const* d_in, const int* in_sizes, int n_in,
                              void* d_out, int out_size)
{
    const float* z   = (const float*)d_in[0];
    const float* W1  = (const float*)d_in[1];
    const float* b1  = (const float*)d_in[2];
    const float* W2  = (const float*)d_in[3];
    const float* b2  = (const float*)d_in[4];
    const int*   ei  = (const int*)d_in[5];
    float*       out = (float*)d_out;

    prep_b_kernel<<<(NCOLS * IN_CH + 255) / 256, 256>>>(W1);

    dim3 grid(NCOLS / BN, (N_NODES + BM - 1) / BM);
    gemm_mma_kernel<<<grid, 256>>>(z);

    int edge_blocks = (N_EDGES * 32 + 255) / 256;
    edge_kernel<<<edge_blocks, 256>>>(ei, b1, W2, b2, out);
}

// round 5
// speedup vs baseline: 2.4703x; 1.3971x over previous
#include <cuda_runtime.h>
#include <cstdint>

#define N_NODES 100000
#define N_EDGES 300000
#define IN_CH   256
#define NCOLS   512

// Scratch (__device__ globals; no allocs allowed)
__device__ float g_C[(size_t)N_NODES * NCOLS];    // layer-1 pre-activation per node (204.8 MB)
__device__ float g_At[(size_t)N_NODES * IN_CH];   // tf32-rounded z (102.4 MB)
__device__ float g_Bt[NCOLS * IN_CH];             // tf32-rounded rearranged W1:
                                                  //  n<256: W1[n][k]; n>=256: W1[n-256][256+k]

__device__ __forceinline__ float tf32r(float x) {
    uint32_t t;
    asm("cvt.rna.tf32.f32 %0, %1;" : "=r"(t) : "f"(x));
    return __uint_as_float(t);
}
__device__ __forceinline__ uint32_t smem_u32(const void* p) {
    uint32_t a;
    asm("{ .reg .u64 t; cvta.to.shared.u64 t, %1; cvt.u32.u64 %0, t; }" : "=r"(a) : "l"(p));
    return a;
}

// ---------------------------------------------------------------------------
// Prep B: g_Bt[n][k] = tf32_rna( n<256 ? W1[n][k] : W1[n-256][256+k] )
// ---------------------------------------------------------------------------
__global__ void prep_b_kernel(const float* __restrict__ W1) {
    int idx = blockIdx.x * blockDim.x + threadIdx.x;
    if (idx >= NCOLS * IN_CH) return;
    int n = idx >> 8;
    int k = idx & 255;
    g_Bt[idx] = tf32r(W1[(n & 255) * 512 + (n >> 8) * 256 + k]);
}

// ---------------------------------------------------------------------------
// Prep A: g_At = tf32_rna(z), vectorized
// ---------------------------------------------------------------------------
__global__ __launch_bounds__(256) void prep_z_kernel(const float* __restrict__ z) {
    int idx = blockIdx.x * blockDim.x + threadIdx.x;     // float4 index
    if (idx >= (N_NODES * IN_CH) / 4) return;
    float4 v = ((const float4*)z)[idx];
    v.x = tf32r(v.x); v.y = tf32r(v.y); v.z = tf32r(v.z); v.w = tf32r(v.w);
    ((float4*)g_At)[idx] = v;
}

// ---------------------------------------------------------------------------
// tf32 mma.sync GEMM, cp.async 3-stage pipeline.
// g_C[M,512] = g_At[M,256] @ g_Bt[512,256]^T
// CTA tile 128x256, BK=32, 256 threads = 8 warps (2x4), warp tile 64x64.
// ---------------------------------------------------------------------------
#define BM 128
#define BN 256
#define BK 32
#define LDK 36                      // padded row stride (floats); (36r+t)%32 == lane -> conflict-free
#define KTILES (IN_CH / BK)         // 8
#define A_F (BM * LDK)              // 4608 floats
#define B_F (BN * LDK)              // 9216 floats
#define STAGE_F (A_F + B_F)         // 13824 floats = 55296 B
#define NSTAGE 3
#define SMEM_BYTES (NSTAGE * STAGE_F * 4)   // 165888

#define CP_ASYNC(dst, src, sz) \
    asm volatile("cp.async.ca.shared.global [%0], [%1], 16, %2;" \
                 :: "r"(dst), "l"(src), "r"(sz))
#define CP_COMMIT()  asm volatile("cp.async.commit_group;" ::: "memory")
#define CP_WAIT2()   asm volatile("cp.async.wait_group 2;" ::: "memory")

__global__ __launch_bounds__(256, 1) void gemm_cp_kernel() {
    extern __shared__ float smem[];
    const uint32_t sb = smem_u32(smem);

    const int tid  = threadIdx.x;
    const int wid  = tid >> 5;
    const int lane = tid & 31;
    const int g = lane >> 2;            // 0..7
    const int t = lane & 3;             // 0..3
    const int wm = (wid & 1) * 64;      // warp M offset
    const int wn = (wid >> 1) * 64;     // warp N offset

    const int m0 = blockIdx.y * BM;
    const int n0 = blockIdx.x * BN;

    float c[4][8][4];
    #pragma unroll
    for (int i = 0; i < 4; i++)
        #pragma unroll
        for (int j = 0; j < 8; j++)
            #pragma unroll
            for (int r = 0; r < 4; r++)
                c[i][j][r] = 0.f;

    // ---- cp.async stage issue: A 4 chunks + B 8 chunks of 16B per thread
    auto issue = [&](int buf, int kt) {
        const uint32_t abase = sb + (uint32_t)(buf * STAGE_F) * 4;
        const uint32_t bbase = abase + A_F * 4;
        #pragma unroll
        for (int i = 0; i < 4; i++) {
            int idx = tid + i * 256;        // 0..1023
            int row = idx >> 3;             // 0..127
            int c16 = idx & 7;              // 0..7 (16B units along K)
            int grow = m0 + row;
            const float* src = g_At + (size_t)grow * IN_CH + kt * BK + c16 * 4;
            uint32_t dst = abase + (uint32_t)(row * LDK + c16 * 4) * 4;
            int sz = (grow < N_NODES) ? 16 : 0;   // OOB rows -> zero-fill
            CP_ASYNC(dst, src, sz);
        }
        #pragma unroll
        for (int i = 0; i < 8; i++) {
            int idx = tid + i * 256;        // 0..2047
            int row = idx >> 3;             // 0..255
            int c16 = idx & 7;
            const float* src = g_Bt + (size_t)(n0 + row) * IN_CH + kt * BK + c16 * 4;
            uint32_t dst = bbase + (uint32_t)(row * LDK + c16 * 4) * 4;
            CP_ASYNC(dst, src, 16);
        }
    };

    // Prologue: fill stages 0..2
    issue(0, 0); CP_COMMIT();
    issue(1, 1); CP_COMMIT();
    issue(2, 2); CP_COMMIT();

    for (int kt = 0; kt < KTILES; kt++) {
        const int buf = kt % NSTAGE;
        CP_WAIT2();                 // group kt complete
        __syncthreads();

        const float* As = smem + buf * STAGE_F;
        const float* Bs = As + A_F;

        #pragma unroll
        for (int ks = 0; ks < 4; ks++) {
            const int kb = ks * 8;
            uint32_t bfr[8][2];
            #pragma unroll
            for (int nf = 0; nf < 8; nf++) {
                const int br = wn + nf * 8 + g;
                bfr[nf][0] = __float_as_uint(Bs[br * LDK + kb + t]);
                bfr[nf][1] = __float_as_uint(Bs[br * LDK + kb + t + 4]);
            }
            #pragma unroll
            for (int mf = 0; mf < 4; mf++) {
                const int ar = wm + mf * 16 + g;
                uint32_t a0 = __float_as_uint(As[ar * LDK + kb + t]);
                uint32_t a1 = __float_as_uint(As[(ar + 8) * LDK + kb + t]);
                uint32_t a2 = __float_as_uint(As[ar * LDK + kb + t + 4]);
                uint32_t a3 = __float_as_uint(As[(ar + 8) * LDK + kb + t + 4]);
                #pragma unroll
                for (int nf = 0; nf < 8; nf++) {
                    asm volatile(
                        "mma.sync.aligned.m16n8k8.row.col.f32.tf32.tf32.f32 "
                        "{%0,%1,%2,%3}, {%4,%5,%6,%7}, {%8,%9}, {%0,%1,%2,%3};"
                        : "+f"(c[mf][nf][0]), "+f"(c[mf][nf][1]),
                          "+f"(c[mf][nf][2]), "+f"(c[mf][nf][3])
                        : "r"(a0), "r"(a1), "r"(a2), "r"(a3),
                          "r"(bfr[nf][0]), "r"(bfr[nf][1]));
                }
            }
        }
        __syncthreads();            // all warps done reading buf
        if (kt + NSTAGE < KTILES) issue(buf, kt + NSTAGE);
        CP_COMMIT();                // uniform group accounting (empty groups OK)
    }

    // Epilogue
    #pragma unroll
    for (int mf = 0; mf < 4; mf++) {
        const int row_a = m0 + wm + mf * 16 + g;
        const int row_b = row_a + 8;
        #pragma unroll
        for (int nf = 0; nf < 8; nf++) {
            const int col = n0 + wn + nf * 8 + t * 2;
            if (row_a < N_NODES)
                *(float2*)&g_C[(size_t)row_a * NCOLS + col] =
                    make_float2(c[mf][nf][0], c[mf][nf][1]);
            if (row_b < N_NODES)
                *(float2*)&g_C[(size_t)row_b * NCOLS + col] =
                    make_float2(c[mf][nf][2], c[mf][nf][3]);
        }
    }
}

// ---------------------------------------------------------------------------
// Edge kernel: one warp per edge.
// out[e] = b2 + sum_h W2[h] * relu(C[src][h] + C[dst][256+h] + b1[h])
// ---------------------------------------------------------------------------
__global__ __launch_bounds__(256) void edge_kernel(
    const int* __restrict__ ei,
    const float* __restrict__ b1,
    const float* __restrict__ W2,
    const float* __restrict__ b2,
    float* __restrict__ out)
{
    int gwarp = (blockIdx.x * blockDim.x + threadIdx.x) >> 5;
    int lane  = threadIdx.x & 31;
    if (gwarp >= N_EDGES) return;

    int s = ei[gwarp];
    int d = ei[N_EDGES + gwarp];

    const float* arow = &g_C[(size_t)s * NCOLS];
    const float* brow = &g_C[(size_t)d * NCOLS + IN_CH];

    float sum = 0.f;
    #pragma unroll
    for (int i = 0; i < 2; i++) {
        int h = (lane + i * 32) << 2;
        float4 av  = *(const float4*)&arow[h];
        float4 bv  = *(const float4*)&brow[h];
        float4 b1v = *(const float4*)&b1[h];
        float4 w2v = *(const float4*)&W2[h];
        sum = fmaf(w2v.x, fmaxf(av.x + bv.x + b1v.x, 0.f), sum);
        sum = fmaf(w2v.y, fmaxf(av.y + bv.y + b1v.y, 0.f), sum);
        sum = fmaf(w2v.z, fmaxf(av.z + bv.z + b1v.z, 0.f), sum);
        sum = fmaf(w2v.w, fmaxf(av.w + bv.w + b1v.w, 0.f), sum);
    }
    #pragma unroll
    for (int o = 16; o; o >>= 1)
        sum += __shfl_xor_sync(0xFFFFFFFFu, sum, o);

    if (lane == 0)
        out[gwarp] = sum + b2[0];
}

// ---------------------------------------------------------------------------
extern "C" void kernel_launch(void* const* d_in, const int* in_sizes, int n_in,
                              void* d_out, int out_size)
{
    const float* z   = (const float*)d_in[0];
    const float* W1  = (const float*)d_in[1];
    const float* b1  = (const float*)d_in[2];
    const float* W2  = (const float*)d_in[3];
    const float* b2  = (const float*)d_in[4];
    const int*   ei  = (const int*)d_in[5];
    float*       out = (float*)d_out;

    cudaFuncSetAttribute(gemm_cp_kernel,
                         cudaFuncAttributeMaxDynamicSharedMemorySize, SMEM_BYTES);

    prep_b_kernel<<<(NCOLS * IN_CH + 255) / 256, 256>>>(W1);
    prep_z_kernel<<<(N_NODES * IN_CH / 4 + 255) / 256, 256>>>(z);

    dim3 grid(NCOLS / BN, (N_NODES + BM - 1) / BM);
    gemm_cp_kernel<<<grid, 256, SMEM_BYTES>>>();

    int edge_blocks = (N_EDGES * 32 + 255) / 256;
    edge_kernel<<<edge_blocks, 256>>>(ei, b1, W2, b2, out);
}

// round 6
// speedup vs baseline: 2.5408x; 1.0285x over previous
#include <cuda_runtime.h>
#include <cuda_fp16.h>
#include <cstdint>

#define N_NODES 100000
#define N_EDGES 300000
#define IN_CH   256
#define NCOLS   512

// Scratch (__device__ globals; no allocs allowed)
__device__ __half g_C[(size_t)N_NODES * NCOLS];   // layer-1 pre-activation, fp16 (102.4 MB)
__device__ float  g_At[(size_t)N_NODES * IN_CH];  // tf32-rounded z (102.4 MB)
__device__ float  g_Bt[NCOLS * IN_CH];            // tf32-rounded rearranged W1:
                                                  //  n<256: W1[n][k]; n>=256: W1[n-256][256+k]

__device__ __forceinline__ float tf32r(float x) {
    uint32_t t;
    asm("cvt.rna.tf32.f32 %0, %1;" : "=r"(t) : "f"(x));
    return __uint_as_float(t);
}
__device__ __forceinline__ uint32_t smem_u32(const void* p) {
    uint32_t a;
    asm("{ .reg .u64 t; cvta.to.shared.u64 t, %1; cvt.u32.u64 %0, t; }" : "=r"(a) : "l"(p));
    return a;
}

// ---------------------------------------------------------------------------
// Prep B: g_Bt[n][k] = tf32_rna( n<256 ? W1[n][k] : W1[n-256][256+k] )
// ---------------------------------------------------------------------------
__global__ void prep_b_kernel(const float* __restrict__ W1) {
    int idx = blockIdx.x * blockDim.x + threadIdx.x;
    if (idx >= NCOLS * IN_CH) return;
    int n = idx >> 8;
    int k = idx & 255;
    g_Bt[idx] = tf32r(W1[(n & 255) * 512 + (n >> 8) * 256 + k]);
}

// ---------------------------------------------------------------------------
// Prep A: g_At = tf32_rna(z), vectorized
// ---------------------------------------------------------------------------
__global__ __launch_bounds__(256) void prep_z_kernel(const float* __restrict__ z) {
    int idx = blockIdx.x * blockDim.x + threadIdx.x;     // float4 index
    if (idx >= (N_NODES * IN_CH) / 4) return;
    float4 v = ((const float4*)z)[idx];
    v.x = tf32r(v.x); v.y = tf32r(v.y); v.z = tf32r(v.z); v.w = tf32r(v.w);
    ((float4*)g_At)[idx] = v;
}

// ---------------------------------------------------------------------------
// tf32 mma.sync GEMM, cp.async 3-stage pipeline.
// g_C[M,512] = fp16( g_At[M,256] @ g_Bt[512,256]^T )
// CTA tile 128x256, BK=32, 256 threads = 8 warps (2x4), warp tile 64x64.
// ---------------------------------------------------------------------------
#define BM 128
#define BN 256
#define BK 32
#define LDK 36                      // padded row stride (floats); conflict-free frag reads
#define KTILES (IN_CH / BK)         // 8
#define A_F (BM * LDK)              // 4608 floats
#define B_F (BN * LDK)              // 9216 floats
#define STAGE_F (A_F + B_F)         // 13824 floats = 55296 B
#define NSTAGE 3
#define SMEM_BYTES (NSTAGE * STAGE_F * 4)   // 165888

#define CP_ASYNC(dst, src, sz) \
    asm volatile("cp.async.ca.shared.global [%0], [%1], 16, %2;" \
                 :: "r"(dst), "l"(src), "r"(sz))
#define CP_COMMIT()  asm volatile("cp.async.commit_group;" ::: "memory")
#define CP_WAIT2()   asm volatile("cp.async.wait_group 2;" ::: "memory")

__global__ __launch_bounds__(256, 1) void gemm_cp_kernel() {
    extern __shared__ float smem[];
    const uint32_t sb = smem_u32(smem);

    const int tid  = threadIdx.x;
    const int wid  = tid >> 5;
    const int lane = tid & 31;
    const int g = lane >> 2;            // 0..7
    const int t = lane & 3;             // 0..3
    const int wm = (wid & 1) * 64;      // warp M offset
    const int wn = (wid >> 1) * 64;     // warp N offset

    const int m0 = blockIdx.y * BM;
    const int n0 = blockIdx.x * BN;

    float c[4][8][4];
    #pragma unroll
    for (int i = 0; i < 4; i++)
        #pragma unroll
        for (int j = 0; j < 8; j++)
            #pragma unroll
            for (int r = 0; r < 4; r++)
                c[i][j][r] = 0.f;

    // ---- cp.async stage issue: A 4 chunks + B 8 chunks of 16B per thread
    auto issue = [&](int buf, int kt) {
        const uint32_t abase = sb + (uint32_t)(buf * STAGE_F) * 4;
        const uint32_t bbase = abase + A_F * 4;
        #pragma unroll
        for (int i = 0; i < 4; i++) {
            int idx = tid + i * 256;        // 0..1023
            int row = idx >> 3;             // 0..127
            int c16 = idx & 7;              // 0..7 (16B units along K)
            int grow = m0 + row;
            const float* src = g_At + (size_t)grow * IN_CH + kt * BK + c16 * 4;
            uint32_t dst = abase + (uint32_t)(row * LDK + c16 * 4) * 4;
            int sz = (grow < N_NODES) ? 16 : 0;   // OOB rows -> zero-fill
            CP_ASYNC(dst, src, sz);
        }
        #pragma unroll
        for (int i = 0; i < 8; i++) {
            int idx = tid + i * 256;        // 0..2047
            int row = idx >> 3;             // 0..255
            int c16 = idx & 7;
            const float* src = g_Bt + (size_t)(n0 + row) * IN_CH + kt * BK + c16 * 4;
            uint32_t dst = bbase + (uint32_t)(row * LDK + c16 * 4) * 4;
            CP_ASYNC(dst, src, 16);
        }
    };

    // Prologue: fill stages 0..2
    issue(0, 0); CP_COMMIT();
    issue(1, 1); CP_COMMIT();
    issue(2, 2); CP_COMMIT();

    for (int kt = 0; kt < KTILES; kt++) {
        const int buf = kt % NSTAGE;
        CP_WAIT2();                 // group kt complete
        __syncthreads();

        const float* As = smem + buf * STAGE_F;
        const float* Bs = As + A_F;

        #pragma unroll
        for (int ks = 0; ks < 4; ks++) {
            const int kb = ks * 8;
            uint32_t bfr[8][2];
            #pragma unroll
            for (int nf = 0; nf < 8; nf++) {
                const int br = wn + nf * 8 + g;
                bfr[nf][0] = __float_as_uint(Bs[br * LDK + kb + t]);
                bfr[nf][1] = __float_as_uint(Bs[br * LDK + kb + t + 4]);
            }
            #pragma unroll
            for (int mf = 0; mf < 4; mf++) {
                const int ar = wm + mf * 16 + g;
                uint32_t a0 = __float_as_uint(As[ar * LDK + kb + t]);
                uint32_t a1 = __float_as_uint(As[(ar + 8) * LDK + kb + t]);
                uint32_t a2 = __float_as_uint(As[ar * LDK + kb + t + 4]);
                uint32_t a3 = __float_as_uint(As[(ar + 8) * LDK + kb + t + 4]);
                #pragma unroll
                for (int nf = 0; nf < 8; nf++) {
                    asm volatile(
                        "mma.sync.aligned.m16n8k8.row.col.f32.tf32.tf32.f32 "
                        "{%0,%1,%2,%3}, {%4,%5,%6,%7}, {%8,%9}, {%0,%1,%2,%3};"
                        : "+f"(c[mf][nf][0]), "+f"(c[mf][nf][1]),
                          "+f"(c[mf][nf][2]), "+f"(c[mf][nf][3])
                        : "r"(a0), "r"(a1), "r"(a2), "r"(a3),
                          "r"(bfr[nf][0]), "r"(bfr[nf][1]));
                }
            }
        }
        __syncthreads();            // all warps done reading buf
        if (kt + NSTAGE < KTILES) issue(buf, kt + NSTAGE);
        CP_COMMIT();                // uniform group accounting (empty groups OK)
    }

    // Epilogue: fp32 accum -> fp16 pairs
    #pragma unroll
    for (int mf = 0; mf < 4; mf++) {
        const int row_a = m0 + wm + mf * 16 + g;
        const int row_b = row_a + 8;
        #pragma unroll
        for (int nf = 0; nf < 8; nf++) {
            const int col = n0 + wn + nf * 8 + t * 2;
            if (row_a < N_NODES)
                *(__half2*)&g_C[(size_t)row_a * NCOLS + col] =
                    __floats2half2_rn(c[mf][nf][0], c[mf][nf][1]);
            if (row_b < N_NODES)
                *(__half2*)&g_C[(size_t)row_b * NCOLS + col] =
                    __floats2half2_rn(c[mf][nf][2], c[mf][nf][3]);
        }
    }
}

// ---------------------------------------------------------------------------
// Edge kernel: one warp per edge, fp16 gathers (16B/lane), fp32 math.
// out[e] = b2 + sum_h W2[h] * relu(C[src][h] + C[dst][256+h] + b1[h])
// ---------------------------------------------------------------------------
__global__ __launch_bounds__(256) void edge_kernel(
    const int* __restrict__ ei,
    const float* __restrict__ b1,
    const float* __restrict__ W2,
    const float* __restrict__ b2,
    float* __restrict__ out)
{
    int gwarp = (blockIdx.x * blockDim.x + threadIdx.x) >> 5;
    int lane  = threadIdx.x & 31;
    if (gwarp >= N_EDGES) return;

    int s = ei[gwarp];
    int d = ei[N_EDGES + gwarp];

    const int h0 = lane * 8;
    const __half* arow = &g_C[(size_t)s * NCOLS];
    const __half* brow = &g_C[(size_t)d * NCOLS + IN_CH];

    uint4 ua = *(const uint4*)(arow + h0);   // 8 halves
    uint4 ub = *(const uint4*)(brow + h0);
    const __half2* ah = (const __half2*)&ua;
    const __half2* bh = (const __half2*)&ub;

    float b1r[8], w2r[8];
    *(float4*)&b1r[0] = *(const float4*)(b1 + h0);
    *(float4*)&b1r[4] = *(const float4*)(b1 + h0 + 4);
    *(float4*)&w2r[0] = *(const float4*)(W2 + h0);
    *(float4*)&w2r[4] = *(const float4*)(W2 + h0 + 4);

    float sum = 0.f;
    #pragma unroll
    for (int i = 0; i < 4; i++) {
        float2 av = __half22float2(ah[i]);
        float2 bv = __half22float2(bh[i]);
        sum = fmaf(w2r[2 * i],     fmaxf(av.x + bv.x + b1r[2 * i],     0.f), sum);
        sum = fmaf(w2r[2 * i + 1], fmaxf(av.y + bv.y + b1r[2 * i + 1], 0.f), sum);
    }
    #pragma unroll
    for (int o = 16; o; o >>= 1)
        sum += __shfl_xor_sync(0xFFFFFFFFu, sum, o);

    if (lane == 0)
        out[gwarp] = sum + b2[0];
}

// ---------------------------------------------------------------------------
extern "C" void kernel_launch(void* const* d_in, const int* in_sizes, int n_in,
                              void* d_out, int out_size)
{
    const float* z   = (const float*)d_in[0];
    const float* W1  = (const float*)d_in[1];
    const float* b1  = (const float*)d_in[2];
    const float* W2  = (const float*)d_in[3];
    const float* b2  = (const float*)d_in[4];
    const int*   ei  = (const int*)d_in[5];
    float*       out = (float*)d_out;

    cudaFuncSetAttribute(gemm_cp_kernel,
                         cudaFuncAttributeMaxDynamicSharedMemorySize, SMEM_BYTES);

    prep_b_kernel<<<(NCOLS * IN_CH + 255) / 256, 256>>>(W1);
    prep_z_kernel<<<(N_NODES * IN_CH / 4 + 255) / 256, 256>>>(z);

    dim3 grid(NCOLS / BN, (N_NODES + BM - 1) / BM);
    gemm_cp_kernel<<<grid, 256, SMEM_BYTES>>>();

    int edge_blocks = (N_EDGES * 32 + 255) / 256;
    edge_kernel<<<edge_blocks, 256>>>(ei, b1, W2, b2, out);
}

// round 7
// speedup vs baseline: 3.7711x; 1.4842x over previous
#include <cuda_runtime.h>
#include <cuda_fp16.h>
#include <cstdint>

#define N_NODES 100000
#define N_EDGES 300000
#define IN_CH   256
#define NCOLS   512

// Scratch (__device__ globals; no allocs allowed)
__device__ __half   g_C[(size_t)N_NODES * NCOLS];    // scaled layer-1 pre-act, fp16 (102.4 MB)
__device__ __half   g_Ah[(size_t)N_NODES * IN_CH];   // fp16 z (51.2 MB)
__device__ __half   g_Bt[NCOLS * IN_CH];             // fp16 rearranged W1 scaled by |W2[h]|
__device__ float    g_b1s[IN_CH];                    // |W2[h]| * b1[h]
__device__ uint32_t g_sgn[8];                        // signbit(W2[h]) bitmask

__device__ __forceinline__ uint32_t smem_u32(const void* p) {
    uint32_t a;
    asm("{ .reg .u64 t; cvta.to.shared.u64 t, %1; cvt.u32.u64 %0, t; }" : "=r"(a) : "l"(p));
    return a;
}

// ---------------------------------------------------------------------------
// Prep B: g_Bt[n][k] = fp16( (n<256 ? W1[n][k] : W1[n-256][256+k]) * |W2[n&255]| )
// Also: g_b1s[h] = |W2[h]|*b1[h];  g_sgn sign bitmask of W2.
// ---------------------------------------------------------------------------
__global__ void prep_b_kernel(const float* __restrict__ W1,
                              const float* __restrict__ W2,
                              const float* __restrict__ b1) {
    int idx = blockIdx.x * blockDim.x + threadIdx.x;
    if (idx < NCOLS * IN_CH) {
        int n = idx >> 8;
        int k = idx & 255;
        int h = n & 255;
        float w = W1[h * 512 + (n >> 8) * 256 + k] * fabsf(W2[h]);
        g_Bt[idx] = __float2half(w);
    }
    if (idx < IN_CH) g_b1s[idx] = fabsf(W2[idx]) * b1[idx];
    if (idx < 8) {
        uint32_t m = 0;
        for (int j = 0; j < 32; j++)
            m |= (__float_as_uint(W2[idx * 32 + j]) >> 31) << j;
        g_sgn[idx] = m;
    }
}

// ---------------------------------------------------------------------------
// Prep A: g_Ah = fp16(z), 8 floats per thread
// ---------------------------------------------------------------------------
__global__ __launch_bounds__(256) void prep_z_kernel(const float* __restrict__ z) {
    int idx = blockIdx.x * blockDim.x + threadIdx.x;
    if (idx >= (N_NODES * IN_CH) / 8) return;
    const float4* zp = (const float4*)z;
    float4 v0 = zp[idx * 2], v1 = zp[idx * 2 + 1];
    union { uint4 u; __half2 h[4]; } o;
    o.h[0] = __floats2half2_rn(v0.x, v0.y);
    o.h[1] = __floats2half2_rn(v0.z, v0.w);
    o.h[2] = __floats2half2_rn(v1.x, v1.y);
    o.h[3] = __floats2half2_rn(v1.z, v1.w);
    ((uint4*)g_Ah)[idx] = o.u;
}

// ---------------------------------------------------------------------------
// fp16 mma.sync GEMM, cp.async 3-stage pipeline.
// g_C[M,512] = fp16( g_Ah[M,256] @ g_Bt[512,256]^T ) (+ bias on dst half)
// CTA tile 128x256, BK=64 halves, 256 threads = 8 warps (2x4), warp 64x64.
// mma.sync.aligned.m16n8k16.row.col.f32.f16.f16.f32
// SMEM rows stored as u32 words (half2 pairs), stride 36 words -> conflict-free.
// ---------------------------------------------------------------------------
#define BM 128
#define BN 256
#define BKH 64                      // K halves per stage (= 32 u32 words)
#define LDW 36                      // row stride in u32 words (32 + 4 pad)
#define KTILES (IN_CH / BKH)        // 4
#define A_W (BM * LDW)              // 4608 words
#define B_W (BN * LDW)              // 9216 words
#define STAGE_W (A_W + B_W)         // 13824 words = 55296 B
#define NSTAGE 3
#define SMEM_BYTES (NSTAGE * STAGE_W * 4)   // 165888

#define CP_ASYNC(dst, src, sz) \
    asm volatile("cp.async.ca.shared.global [%0], [%1], 16, %2;" \
                 :: "r"(dst), "l"(src), "r"(sz))
#define CP_COMMIT()  asm volatile("cp.async.commit_group;" ::: "memory")
#define CP_WAIT2()   asm volatile("cp.async.wait_group 2;" ::: "memory")

__global__ __launch_bounds__(256, 1) void gemm_fp16_kernel() {
    extern __shared__ uint32_t smw[];
    const uint32_t sb = smem_u32(smw);

    const int tid  = threadIdx.x;
    const int wid  = tid >> 5;
    const int lane = tid & 31;
    const int g = lane >> 2;            // 0..7
    const int t = lane & 3;             // 0..3
    const int wm = (wid & 1) * 64;
    const int wn = (wid >> 1) * 64;

    const int m0 = blockIdx.y * BM;
    const int n0 = blockIdx.x * BN;

    float c[4][8][4];
    #pragma unroll
    for (int i = 0; i < 4; i++)
        #pragma unroll
        for (int j = 0; j < 8; j++)
            #pragma unroll
            for (int r = 0; r < 4; r++)
                c[i][j][r] = 0.f;

    // ---- cp.async stage issue: A 4 chunks + B 8 chunks of 16B per thread
    auto issue = [&](int buf, int kt) {
        const uint32_t abase = sb + (uint32_t)(buf * STAGE_W) * 4;
        const uint32_t bbase = abase + A_W * 4;
        #pragma unroll
        for (int i = 0; i < 4; i++) {
            int idx = tid + i * 256;        // 0..1023
            int row = idx >> 3;             // 0..127
            int c16 = idx & 7;              // 16B chunk along K (8 halves)
            int grow = m0 + row;
            const __half* src = g_Ah + (size_t)grow * IN_CH + kt * BKH + c16 * 8;
            uint32_t dst = abase + (uint32_t)(row * LDW + c16 * 4) * 4;
            int sz = (grow < N_NODES) ? 16 : 0;
            CP_ASYNC(dst, src, sz);
        }
        #pragma unroll
        for (int i = 0; i < 8; i++) {
            int idx = tid + i * 256;        // 0..2047
            int row = idx >> 3;             // 0..255
            int c16 = idx & 7;
            const __half* src = g_Bt + (size_t)(n0 + row) * IN_CH + kt * BKH + c16 * 8;
            uint32_t dst = bbase + (uint32_t)(row * LDW + c16 * 4) * 4;
            CP_ASYNC(dst, src, 16);
        }
    };

    issue(0, 0); CP_COMMIT();
    issue(1, 1); CP_COMMIT();
    issue(2, 2); CP_COMMIT();

    for (int kt = 0; kt < KTILES; kt++) {
        const int buf = kt % NSTAGE;
        CP_WAIT2();
        __syncthreads();

        const uint32_t* As = smw + buf * STAGE_W;
        const uint32_t* Bs = As + A_W;

        #pragma unroll
        for (int s = 0; s < 4; s++) {       // 4 k16 steps per BKH=64
            const int kb = s * 8;           // word offset
            uint32_t bfr[8][2];
            #pragma unroll
            for (int nf = 0; nf < 8; nf++) {
                const int br = wn + nf * 8 + g;
                bfr[nf][0] = Bs[br * LDW + kb + t];
                bfr[nf][1] = Bs[br * LDW + kb + t + 4];
            }
            #pragma unroll
            for (int mf = 0; mf < 4; mf++) {
                const int ar = wm + mf * 16 + g;
                uint32_t a0 = As[ar * LDW + kb + t];
                uint32_t a1 = As[(ar + 8) * LDW + kb + t];
                uint32_t a2 = As[ar * LDW + kb + t + 4];
                uint32_t a3 = As[(ar + 8) * LDW + kb + t + 4];
                #pragma unroll
                for (int nf = 0; nf < 8; nf++) {
                    asm volatile(
                        "mma.sync.aligned.m16n8k16.row.col.f32.f16.f16.f32 "
                        "{%0,%1,%2,%3}, {%4,%5,%6,%7}, {%8,%9}, {%0,%1,%2,%3};"
                        : "+f"(c[mf][nf][0]), "+f"(c[mf][nf][1]),
                          "+f"(c[mf][nf][2]), "+f"(c[mf][nf][3])
                        : "r"(a0), "r"(a1), "r"(a2), "r"(a3),
                          "r"(bfr[nf][0]), "r"(bfr[nf][1]));
                }
            }
        }
        __syncthreads();
        if (kt + NSTAGE < KTILES) issue(buf, kt + NSTAGE);
        CP_COMMIT();
    }

    // Epilogue: add scaled bias on dst half, convert to fp16
    const bool dsthalf = (n0 >= 256);
    #pragma unroll
    for (int mf = 0; mf < 4; mf++) {
        const int row_a = m0 + wm + mf * 16 + g;
        const int row_b = row_a + 8;
        #pragma unroll
        for (int nf = 0; nf < 8; nf++) {
            const int colh = wn + nf * 8 + t * 2;       // 0..255 within half
            float bx = 0.f, by = 0.f;
            if (dsthalf) { bx = g_b1s[colh]; by = g_b1s[colh + 1]; }
            const int col = n0 + colh;
            if (row_a < N_NODES)
                *(__half2*)&g_C[(size_t)row_a * NCOLS + col] =
                    __floats2half2_rn(c[mf][nf][0] + bx, c[mf][nf][1] + by);
            if (row_b < N_NODES)
                *(__half2*)&g_C[(size_t)row_b * NCOLS + col] =
                    __floats2half2_rn(c[mf][nf][2] + bx, c[mf][nf][3] + by);
        }
    }
}

// ---------------------------------------------------------------------------
// Edge kernel: one warp per edge; only the two gathered rows + sign mask.
// out[e] = b2 + sum_h sign(W2[h]) * relu(Cs[src][h] + Cd[dst][h])
// ---------------------------------------------------------------------------
__global__ __launch_bounds__(256) void edge_kernel(
    const int* __restrict__ ei,
    const float* __restrict__ b2,
    float* __restrict__ out)
{
    int gwarp = (blockIdx.x * blockDim.x + threadIdx.x) >> 5;
    int lane  = threadIdx.x & 31;
    if (gwarp >= N_EDGES) return;

    int s = ei[gwarp];
    int d = ei[N_EDGES + gwarp];

    const int h0 = lane * 8;
    union { uint4 u; __half2 h[4]; } ua, ub;
    ua.u = *(const uint4*)(&g_C[(size_t)s * NCOLS] + h0);
    ub.u = *(const uint4*)(&g_C[(size_t)d * NCOLS + IN_CH] + h0);

    uint32_t m8 = (g_sgn[lane >> 2] >> ((lane & 3) * 8)) & 0xFF;

    float sum = 0.f;
    #pragma unroll
    for (int i = 0; i < 4; i++) {
        float2 av = __half22float2(ua.h[i]);
        float2 bv = __half22float2(ub.h[i]);
        float r0 = fmaxf(av.x + bv.x, 0.f);
        float r1 = fmaxf(av.y + bv.y, 0.f);
        sum += __uint_as_float(__float_as_uint(r0) ^ ((m8 >> (2 * i)) & 1u) << 31);
        sum += __uint_as_float(__float_as_uint(r1) ^ ((m8 >> (2 * i + 1)) & 1u) << 31);
    }
    #pragma unroll
    for (int o = 16; o; o >>= 1)
        sum += __shfl_xor_sync(0xFFFFFFFFu, sum, o);

    if (lane == 0)
        out[gwarp] = sum + b2[0];
}

// ---------------------------------------------------------------------------
extern "C" void kernel_launch(void* const* d_in, const int* in_sizes, int n_in,
                              void* d_out, int out_size)
{
    const float* z   = (const float*)d_in[0];
    const float* W1  = (const float*)d_in[1];
    const float* b1  = (const float*)d_in[2];
    const float* W2  = (const float*)d_in[3];
    const float* b2  = (const float*)d_in[4];
    const int*   ei  = (const int*)d_in[5];
    float*       out = (float*)d_out;

    cudaFuncSetAttribute(gemm_fp16_kernel,
                         cudaFuncAttributeMaxDynamicSharedMemorySize, SMEM_BYTES);

    prep_b_kernel<<<(NCOLS * IN_CH + 255) / 256, 256>>>(W1, W2, b1);
    prep_z_kernel<<<(N_NODES * IN_CH / 8 + 255) / 256, 256>>>(z);

    dim3 grid(NCOLS / BN, (N_NODES + BM - 1) / BM);
    gemm_fp16_kernel<<<grid, 256, SMEM_BYTES>>>();

    int edge_blocks = (N_EDGES * 32 + 255) / 256;
    edge_kernel<<<edge_blocks, 256>>>(ei, b2, out);
}

// round 8
// speedup vs baseline: 4.1846x; 1.1097x over previous
#include <cuda_runtime.h>
#include <cuda_fp16.h>
#include <cstdint>

#define N_NODES 100000
#define N_EDGES 300000
#define IN_CH   256
#define NCOLS   512

// Scratch (__device__ globals; no allocs allowed)
__device__ __half   g_C[(size_t)N_NODES * NCOLS];    // scaled layer-1 pre-act, fp16 (102.4 MB)
__device__ __half   g_Ah[(size_t)N_NODES * IN_CH];   // fp16 z (51.2 MB)
__device__ __half   g_Bt[NCOLS * IN_CH];             // fp16 rearranged W1 scaled by |W2[h]|
__device__ float    g_b1s[IN_CH];                    // |W2[h]| * b1[h]
__device__ uint32_t g_sgn[8];                        // signbit(W2[h]) bitmask

__device__ __forceinline__ uint32_t smem_u32(const void* p) {
    uint32_t a;
    asm("{ .reg .u64 t; cvta.to.shared.u64 t, %1; cvt.u32.u64 %0, t; }" : "=r"(a) : "l"(p));
    return a;
}

// ---------------------------------------------------------------------------
// Prep B: g_Bt[n][k] = fp16( (n<256 ? W1[n][k] : W1[n-256][256+k]) * |W2[n&255]| )
// Also: g_b1s[h] = |W2[h]|*b1[h];  g_sgn sign bitmask of W2.
// ---------------------------------------------------------------------------
__global__ void prep_b_kernel(const float* __restrict__ W1,
                              const float* __restrict__ W2,
                              const float* __restrict__ b1) {
    int idx = blockIdx.x * blockDim.x + threadIdx.x;
    if (idx < NCOLS * IN_CH) {
        int n = idx >> 8;
        int k = idx & 255;
        int h = n & 255;
        float w = W1[h * 512 + (n >> 8) * 256 + k] * fabsf(W2[h]);
        g_Bt[idx] = __float2half(w);
    }
    if (idx < IN_CH) g_b1s[idx] = fabsf(W2[idx]) * b1[idx];
    if (idx < 8) {
        uint32_t m = 0;
        for (int j = 0; j < 32; j++)
            m |= (__float_as_uint(W2[idx * 32 + j]) >> 31) << j;
        g_sgn[idx] = m;
    }
}

// ---------------------------------------------------------------------------
// Prep A: g_Ah = fp16(z), 8 floats per thread
// ---------------------------------------------------------------------------
__global__ __launch_bounds__(256) void prep_z_kernel(const float* __restrict__ z) {
    int idx = blockIdx.x * blockDim.x + threadIdx.x;
    if (idx >= (N_NODES * IN_CH) / 8) return;
    const float4* zp = (const float4*)z;
    float4 v0 = zp[idx * 2], v1 = zp[idx * 2 + 1];
    union { uint4 u; __half2 h[4]; } o;
    o.h[0] = __floats2half2_rn(v0.x, v0.y);
    o.h[1] = __floats2half2_rn(v0.z, v0.w);
    o.h[2] = __floats2half2_rn(v1.x, v1.y);
    o.h[3] = __floats2half2_rn(v1.z, v1.w);
    ((uint4*)g_Ah)[idx] = o.u;
}

// ---------------------------------------------------------------------------
// fp16 mma.sync GEMM, cp.async 3-stage pipeline, ldmatrix A fragments.
// g_C[M,512] = fp16( g_Ah[M,256] @ g_Bt[512,256]^T ) (+ bias on dst half)
// CTA tile 128x256, BK=64 halves, 256 threads = 8 warps (2x4), warp 64x64.
// ---------------------------------------------------------------------------
#define BM 128
#define BN 256
#define BKH 64                      // K halves per stage (= 32 u32 words)
#define LDW 36                      // row stride in u32 words (32 + 4 pad)
#define KTILES (IN_CH / BKH)        // 4
#define A_W (BM * LDW)              // 4608 words
#define B_W (BN * LDW)              // 9216 words
#define STAGE_W (A_W + B_W)         // 13824 words = 55296 B
#define NSTAGE 3
#define SMEM_BYTES (NSTAGE * STAGE_W * 4)   // 165888

#define CP_ASYNC(dst, src, sz) \
    asm volatile("cp.async.ca.shared.global [%0], [%1], 16, %2;" \
                 :: "r"(dst), "l"(src), "r"(sz))
#define CP_COMMIT()  asm volatile("cp.async.commit_group;" ::: "memory")
#define CP_WAIT2()   asm volatile("cp.async.wait_group 2;" ::: "memory")

__global__ __launch_bounds__(256, 1) void gemm_fp16_kernel() {
    extern __shared__ uint32_t smw[];
    const uint32_t sb = smem_u32(smw);

    const int tid  = threadIdx.x;
    const int wid  = tid >> 5;
    const int lane = tid & 31;
    const int g = lane >> 2;            // 0..7
    const int t = lane & 3;             // 0..3
    const int wm = (wid & 1) * 64;
    const int wn = (wid >> 1) * 64;

    const int m0 = blockIdx.y * BM;
    const int n0 = blockIdx.x * BN;

    // ldmatrix.x4 per-lane word offset within the A tile:
    // lanes 0-15 -> rows wm+0..15 at word col 0; lanes 16-31 -> same rows at +4 words (k+8 halves)
    const uint32_t a_lm_word = (uint32_t)((wm + (lane & 15)) * LDW + (lane >> 4) * 4);

    float c[4][8][4];
    #pragma unroll
    for (int i = 0; i < 4; i++)
        #pragma unroll
        for (int j = 0; j < 8; j++)
            #pragma unroll
            for (int r = 0; r < 4; r++)
                c[i][j][r] = 0.f;

    // ---- cp.async stage issue: A 4 chunks + B 8 chunks of 16B per thread
    auto issue = [&](int buf, int kt) {
        const uint32_t abase = sb + (uint32_t)(buf * STAGE_W) * 4;
        const uint32_t bbase = abase + A_W * 4;
        #pragma unroll
        for (int i = 0; i < 4; i++) {
            int idx = tid + i * 256;        // 0..1023
            int row = idx >> 3;             // 0..127
            int c16 = idx & 7;              // 16B chunk along K (8 halves)
            int grow = m0 + row;
            const __half* src = g_Ah + (size_t)grow * IN_CH + kt * BKH + c16 * 8;
            uint32_t dst = abase + (uint32_t)(row * LDW + c16 * 4) * 4;
            int sz = (grow < N_NODES) ? 16 : 0;
            CP_ASYNC(dst, src, sz);
        }
        #pragma unroll
        for (int i = 0; i < 8; i++) {
            int idx = tid + i * 256;        // 0..2047
            int row = idx >> 3;             // 0..255
            int c16 = idx & 7;
            const __half* src = g_Bt + (size_t)(n0 + row) * IN_CH + kt * BKH + c16 * 8;
            uint32_t dst = bbase + (uint32_t)(row * LDW + c16 * 4) * 4;
            CP_ASYNC(dst, src, 16);
        }
    };

    issue(0, 0); CP_COMMIT();
    issue(1, 1); CP_COMMIT();
    issue(2, 2); CP_COMMIT();

    for (int kt = 0; kt < KTILES; kt++) {
        const int buf = kt % NSTAGE;
        CP_WAIT2();
        __syncthreads();

        const uint32_t abase = sb + (uint32_t)(buf * STAGE_W) * 4;
        const uint32_t* Bs = smw + buf * STAGE_W + A_W;
        const uint32_t a_lm_base = abase + a_lm_word * 4;

        #pragma unroll
        for (int s = 0; s < 4; s++) {       // 4 k16 steps per BKH=64
            const int kb = s * 8;           // word offset
            uint32_t bfr[8][2];
            #pragma unroll
            for (int nf = 0; nf < 8; nf++) {
                const int br = wn + nf * 8 + g;
                bfr[nf][0] = Bs[br * LDW + kb + t];
                bfr[nf][1] = Bs[br * LDW + kb + t + 4];
            }
            #pragma unroll
            for (int mf = 0; mf < 4; mf++) {
                uint32_t a0, a1, a2, a3;
                uint32_t aaddr = a_lm_base + (uint32_t)(mf * 16 * LDW + kb) * 4;
                asm volatile(
                    "ldmatrix.sync.aligned.m8n8.x4.shared.b16 {%0,%1,%2,%3}, [%4];"
                    : "=r"(a0), "=r"(a1), "=r"(a2), "=r"(a3) : "r"(aaddr));
                #pragma unroll
                for (int nf = 0; nf < 8; nf++) {
                    asm volatile(
                        "mma.sync.aligned.m16n8k16.row.col.f32.f16.f16.f32 "
                        "{%0,%1,%2,%3}, {%4,%5,%6,%7}, {%8,%9}, {%0,%1,%2,%3};"
                        : "+f"(c[mf][nf][0]), "+f"(c[mf][nf][1]),
                          "+f"(c[mf][nf][2]), "+f"(c[mf][nf][3])
                        : "r"(a0), "r"(a1), "r"(a2), "r"(a3),
                          "r"(bfr[nf][0]), "r"(bfr[nf][1]));
                }
            }
        }
        __syncthreads();
        if (kt + NSTAGE < KTILES) issue(buf, kt + NSTAGE);
        CP_COMMIT();
    }

    // Epilogue: add scaled bias on dst half, convert to fp16
    const bool dsthalf = (n0 >= 256);
    #pragma unroll
    for (int mf = 0; mf < 4; mf++) {
        const int row_a = m0 + wm + mf * 16 + g;
        const int row_b = row_a + 8;
        #pragma unroll
        for (int nf = 0; nf < 8; nf++) {
            const int colh = wn + nf * 8 + t * 2;       // 0..255 within half
            float bx = 0.f, by = 0.f;
            if (dsthalf) { bx = g_b1s[colh]; by = g_b1s[colh + 1]; }
            const int col = n0 + colh;
            if (row_a < N_NODES)
                *(__half2*)&g_C[(size_t)row_a * NCOLS + col] =
                    __floats2half2_rn(c[mf][nf][0] + bx, c[mf][nf][1] + by);
            if (row_b < N_NODES)
                *(__half2*)&g_C[(size_t)row_b * NCOLS + col] =
                    __floats2half2_rn(c[mf][nf][2] + bx, c[mf][nf][3] + by);
        }
    }
}

// ---------------------------------------------------------------------------
// Edge kernel: TWO edges per warp (16 lanes each, 16 channels per lane).
// out[e] = b2 + sum_h sign(W2[h]) * relu(Cs[src][h] + Cd[dst][h])
// ---------------------------------------------------------------------------
__global__ __launch_bounds__(256) void edge_kernel(
    const int* __restrict__ ei,
    const float* __restrict__ b2,
    float* __restrict__ out)
{
    int warp = (blockIdx.x * blockDim.x + threadIdx.x) >> 5;
    int lane = threadIdx.x & 31;
    int half = lane >> 4;               // which edge within the warp
    int sl   = lane & 15;               // sub-lane within the edge

    int e = warp * 2 + half;
    if (e >= N_EDGES) return;

    int s = ei[e];
    int d = ei[N_EDGES + e];

    const __half* arow = &g_C[(size_t)s * NCOLS] + sl * 16;
    const __half* brow = &g_C[(size_t)d * NCOLS + IN_CH] + sl * 16;

    union { uint4 u; __half2 h[4]; } ua0, ua1, ub0, ub1;
    ua0.u = *(const uint4*)(arow);
    ua1.u = *(const uint4*)(arow + 8);
    ub0.u = *(const uint4*)(brow);
    ub1.u = *(const uint4*)(brow + 8);

    // 16 sign bits for channels sl*16 .. sl*16+15
    uint32_t m16 = (g_sgn[sl >> 1] >> ((sl & 1) * 16)) & 0xFFFFu;

    float sum = 0.f;
    #pragma unroll
    for (int i = 0; i < 4; i++) {
        float2 av = __half22float2(ua0.h[i]);
        float2 bv = __half22float2(ub0.h[i]);
        float r0 = fmaxf(av.x + bv.x, 0.f);
        float r1 = fmaxf(av.y + bv.y, 0.f);
        sum += __uint_as_float(__float_as_uint(r0) ^ (((m16 >> (2 * i)) & 1u) << 31));
        sum += __uint_as_float(__float_as_uint(r1) ^ (((m16 >> (2 * i + 1)) & 1u) << 31));
    }
    #pragma unroll
    for (int i = 0; i < 4; i++) {
        float2 av = __half22float2(ua1.h[i]);
        float2 bv = __half22float2(ub1.h[i]);
        float r0 = fmaxf(av.x + bv.x, 0.f);
        float r1 = fmaxf(av.y + bv.y, 0.f);
        sum += __uint_as_float(__float_as_uint(r0) ^ (((m16 >> (8 + 2 * i)) & 1u) << 31));
        sum += __uint_as_float(__float_as_uint(r1) ^ (((m16 >> (8 + 2 * i + 1)) & 1u) << 31));
    }

    // Reduce within each 16-lane half
    #pragma unroll
    for (int o = 8; o; o >>= 1)
        sum += __shfl_xor_sync(0xFFFFFFFFu, sum, o);

    if (sl == 0)
        out[e] = sum + b2[0];
}

// ---------------------------------------------------------------------------
extern "C" void kernel_launch(void* const* d_in, const int* in_sizes, int n_in,
                              void* d_out, int out_size)
{
    const float* z   = (const float*)d_in[0];
    const float* W1  = (const float*)d_in[1];
    const float* b1  = (const float*)d_in[2];
    const float* W2  = (const float*)d_in[3];
    const float* b2  = (const float*)d_in[4];
    const int*   ei  = (const int*)d_in[5];
    float*       out = (float*)d_out;

    cudaFuncSetAttribute(gemm_fp16_kernel,
                         cudaFuncAttributeMaxDynamicSharedMemorySize, SMEM_BYTES);

    prep_b_kernel<<<(NCOLS * IN_CH + 255) / 256, 256>>>(W1, W2, b1);
    prep_z_kernel<<<(N_NODES * IN_CH / 8 + 255) / 256, 256>>>(z);

    dim3 grid(NCOLS / BN, (N_NODES + BM - 1) / BM);
    gemm_fp16_kernel<<<grid, 256, SMEM_BYTES>>>();

    int edge_blocks = (N_EDGES / 2 + 7) / 8;   // 8 warps/block, 2 edges/warp
    edge_kernel<<<edge_blocks, 256>>>(ei, b2, out);
}